// round 1
// baseline (speedup 1.0000x reference)
#include <cuda_runtime.h>
#include <math.h>

#define HH 256
#define WW 256
#define BB 4
#define CIN 128
#define NOC 128   // 64 (branch a) + 64 (branch b)

// ---------------- device scratch (no allocations allowed) ----------------
__device__ float g_wT[CIN * 9 * NOC];   // [cin][tap][oc], BN scale folded
__device__ float g_bfold[NOC];          // folded conv bias + BN shift
__device__ float g_attw[NOC];           // per-channel 1x1 attention weight
__device__ float g_att[2 * BB * HH * WW]; // post-BN attention logits, [branch][b][h][w]

// ---------------- kernel 0: weight transpose + BN fold ----------------
__global__ void setup_kernel(
    const float* __restrict__ wa, const float* __restrict__ ba,
    const float* __restrict__ wb, const float* __restrict__ bb,
    const float* __restrict__ ga, const float* __restrict__ bta,
    const float* __restrict__ ma, const float* __restrict__ va,
    const float* __restrict__ gb, const float* __restrict__ btb,
    const float* __restrict__ mb, const float* __restrict__ vb,
    const float* __restrict__ attaw, const float* __restrict__ attbw)
{
    int idx = blockIdx.x * blockDim.x + threadIdx.x;
    if (idx < NOC) {
        int oc = idx;
        bool isa = oc < 64;
        int o = isa ? oc : oc - 64;
        float gamma = isa ? ga[o] : gb[o];
        float beta  = isa ? bta[o] : btb[o];
        float mean  = isa ? ma[o] : mb[o];
        float var   = isa ? va[o] : vb[o];
        float A = gamma / sqrtf(var + 1e-3f);
        float bias = isa ? ba[o] : bb[o];
        g_bfold[oc] = (bias - mean) * A + beta;
        g_attw[oc]  = isa ? attaw[o] : attbw[o];
    }
    if (idx < CIN * 9 * NOC) {
        int oc  = idx % NOC;
        int tap = (idx / NOC) % 9;
        int cin = idx / (NOC * 9);
        bool isa = oc < 64;
        int o = isa ? oc : oc - 64;
        float gamma = isa ? ga[o] : gb[o];
        float var   = isa ? va[o] : vb[o];
        float A = gamma / sqrtf(var + 1e-3f);
        const float* w = isa ? wa : wb;
        g_wT[idx] = w[(o * CIN + cin) * 9 + tap] * A;
    }
}

// ---------------- kernel 1: fused dual-branch conv3x3 + BN + 1x1 attention logit ----------------
// Block: 256 threads. Tile: all 128 oc x (4h x 32w) pixels.
// Thread: ocg = tid>>4 (16 groups of 8 oc), pg = tid&15 -> (row 0..3, 8-wide col group).
__global__ void __launch_bounds__(256) conv_att_kernel(
    const float* __restrict__ x, float* __restrict__ out,
    const float* __restrict__ attaw, const float* __restrict__ attab,
    const float* __restrict__ attbw, const float* __restrict__ attbb,
    const float* __restrict__ abga, const float* __restrict__ abba,
    const float* __restrict__ abma, const float* __restrict__ abva,
    const float* __restrict__ abgb, const float* __restrict__ abbb,
    const float* __restrict__ abmb, const float* __restrict__ abvb)
{
    __shared__ float ws[8 * 9 * 128];      // weights chunk [ci][tap][oc]; reused as attpart later
    __shared__ float xs[8][6][34];         // input chunk with halo

    const int tid = threadIdx.x;
    const int b   = blockIdx.z;
    const int gy0 = blockIdx.y * 4;
    const int gx0 = blockIdx.x * 32;
    const int ocg = tid >> 4;
    const int pg  = tid & 15;
    const int prow = pg >> 2;
    const int c0   = (pg & 3) * 8;

    float acc[8][8];
    #pragma unroll
    for (int o = 0; o < 8; o++)
        #pragma unroll
        for (int p = 0; p < 8; p++) acc[o][p] = 0.f;

    for (int cin0 = 0; cin0 < CIN; cin0 += 8) {
        __syncthreads();
        // stage input tile (zero-padded halo)
        for (int i = tid; i < 8 * 6 * 34; i += 256) {
            int col = i % 34;
            int row = (i / 34) % 6;
            int ci  = i / 204;
            int gy = gy0 - 1 + row;
            int gx = gx0 - 1 + col;
            float v = 0.f;
            if ((unsigned)gy < HH && (unsigned)gx < WW)
                v = x[(((size_t)b * CIN + cin0 + ci) * HH + gy) * WW + gx];
            xs[ci][row][col] = v;
        }
        // stage weights (fully coalesced from pre-transposed buffer)
        const float* wsrc = g_wT + cin0 * 9 * NOC;
        for (int i = tid; i < 8 * 9 * 128; i += 256)
            ws[i] = wsrc[i];
        __syncthreads();

        for (int ci = 0; ci < 8; ci++) {
            float xin[3][10];
            #pragma unroll
            for (int rr = 0; rr < 3; rr++)
                #pragma unroll
                for (int cc = 0; cc < 10; cc++)
                    xin[rr][cc] = xs[ci][prow + rr][c0 + cc];
            #pragma unroll
            for (int o = 0; o < 8; o++) {
                const float* wp = ws + ci * 9 * 128 + ocg * 8 + o;
                float wr[9];
                #pragma unroll
                for (int t = 0; t < 9; t++) wr[t] = wp[t * 128];
                #pragma unroll
                for (int rr = 0; rr < 3; rr++)
                    #pragma unroll
                    for (int ss = 0; ss < 3; ss++)
                        #pragma unroll
                        for (int p = 0; p < 8; p++)
                            acc[o][p] = fmaf(wr[rr * 3 + ss], xin[rr][ss + p], acc[o][p]);
            }
        }
    }

    // ---------------- epilogue: BN-folded bias, store f, attention partials ----------------
    const int gy  = gy0 + prow;
    const int gxb = gx0 + c0;
    float attp[8];
    #pragma unroll
    for (int p = 0; p < 8; p++) attp[p] = 0.f;

    #pragma unroll
    for (int o = 0; o < 8; o++) {
        int oc = ocg * 8 + o;
        float bf = g_bfold[oc];
        float aw = g_attw[oc];
        float f[8];
        #pragma unroll
        for (int p = 0; p < 8; p++) {
            f[p] = acc[o][p] + bf;
            attp[p] = fmaf(aw, f[p], attp[p]);
        }
        float* op = out + (((size_t)b * NOC + oc) * HH + gy) * WW + gxb;
        *(float4*)op       = make_float4(f[0], f[1], f[2], f[3]);
        *(float4*)(op + 4) = make_float4(f[4], f[5], f[6], f[7]);
    }

    __syncthreads();                 // all ws (weight) reads done -> safe to reuse
    float* attpart = ws;             // [16 ocg][128 pix], deterministic reduction
    #pragma unroll
    for (int p = 0; p < 8; p++)
        attpart[ocg * 128 + prow * 32 + c0 + p] = attp[p];
    __syncthreads();

    {
        int branch = tid >> 7;       // 0: a, 1: b
        int pix = tid & 127;
        float s = 0.f;
        #pragma unroll
        for (int g = 0; g < 8; g++)
            s += attpart[(branch * 8 + g) * 128 + pix];
        int row = pix >> 5, col = pix & 31;
        int yy = gy0 + row, xx = gx0 + col;
        float gh = fabsf((float)yy - 127.5f) * (1.f / 128.f);
        float gw = fabsf((float)xx - 127.5f) * (1.f / 128.f);
        const float* awp = branch ? attbw : attaw;
        float pre = s + awp[64] * gh + awp[65] * gw + (branch ? attbb[0] : attab[0]);
        float gm = branch ? abgb[0] : abga[0];
        float bt = branch ? abbb[0] : abba[0];
        float mn = branch ? abmb[0] : abma[0];
        float vr = branch ? abvb[0] : abva[0];
        float av = (pre - mn) * gm / sqrtf(vr + 1e-5f) + bt;
        g_att[(((size_t)branch * BB + b) * HH + yy) * WW + xx] = av;
    }
}

// ---------------- kernel 2: 3x3 attention conv + sigmoid + in-place gating ----------------
__global__ void __launch_bounds__(256) map_kernel(
    float* __restrict__ out,
    const float* __restrict__ wa, const float* __restrict__ wb,
    const float* __restrict__ s1, const float* __restrict__ s2)
{
    __shared__ float swa[36], swb[36];
    int t = threadIdx.y * 32 + threadIdx.x;
    if (t < 36) { swa[t] = wa[t]; swb[t] = wb[t]; }
    __syncthreads();

    int b   = blockIdx.z;
    int gy  = blockIdx.y * 8 + threadIdx.y;
    int gx4 = blockIdx.x * 128 + threadIdx.x * 4;

    const float prmax = 1.41421356237f * (127.5f / 128.f);
    const float prmin = 1.41421356237f * (0.5f / 128.f);
    const float prk = 2.f / (prmax - prmin);
    const float prc = 1.f - prmax * prk;

    float scl1 = s1[0], scl2 = s2[0];
    float mapa[4], mapb[4];
    #pragma unroll
    for (int p = 0; p < 4; p++) {
        int gx = gx4 + p;
        float sa = 0.f, sb = 0.f;
        #pragma unroll
        for (int rr = 0; rr < 3; rr++) {
            int y = gy + rr - 1;
            if ((unsigned)y >= HH) continue;
            #pragma unroll
            for (int ss = 0; ss < 3; ss++) {
                int xq = gx + ss - 1;
                if ((unsigned)xq >= WW) continue;
                float av = g_att[(((size_t)0 * BB + b) * HH + y) * WW + xq];
                float bv = g_att[(((size_t)1 * BB + b) * HH + y) * WW + xq];
                float gh = fabsf((float)y  - 127.5f) * (1.f / 128.f);
                float gw = fabsf((float)xq - 127.5f) * (1.f / 128.f);
                float pr = prk * sqrtf(gh * gh + gw * gw) + prc;
                int tap = rr * 3 + ss;
                sa += swa[tap] * av + swa[9 + tap] * gh + swa[18 + tap] * gw + swa[27 + tap] * pr;
                sb += swb[tap] * bv + swb[9 + tap] * gh + swb[18 + tap] * gw + swb[27 + tap] * pr;
            }
        }
        mapa[p] = scl1 / (1.f + expf(-sa));
        mapb[p] = scl2 / (1.f + expf(-sb));
    }

    size_t base = (((size_t)b * NOC) * HH + gy) * WW + gx4;
    #pragma unroll 4
    for (int oc = 0; oc < NOC; oc++) {
        float4 v = *(float4*)(out + base + (size_t)oc * HH * WW);
        if (oc < 64) { v.x *= mapa[0]; v.y *= mapa[1]; v.z *= mapa[2]; v.w *= mapa[3]; }
        else         { v.x *= mapb[0]; v.y *= mapb[1]; v.z *= mapb[2]; v.w *= mapb[3]; }
        *(float4*)(out + base + (size_t)oc * HH * WW) = v;
    }
}

// ---------------- launch ----------------
extern "C" void kernel_launch(void* const* d_in, const int* in_sizes, int n_in,
                              void* d_out, int out_size)
{
    const float* x     = (const float*)d_in[0];
    const float* caw   = (const float*)d_in[1];
    const float* cab   = (const float*)d_in[2];
    const float* cbw   = (const float*)d_in[3];
    const float* cbb   = (const float*)d_in[4];
    const float* bag   = (const float*)d_in[5];
    const float* babt  = (const float*)d_in[6];
    const float* bam   = (const float*)d_in[7];
    const float* bav   = (const float*)d_in[8];
    const float* bbg   = (const float*)d_in[9];
    const float* bbbt  = (const float*)d_in[10];
    const float* bbm   = (const float*)d_in[11];
    const float* bbv   = (const float*)d_in[12];
    const float* attaw = (const float*)d_in[13];
    const float* attab = (const float*)d_in[14];
    const float* attbw = (const float*)d_in[15];
    const float* attbb = (const float*)d_in[16];
    const float* abga  = (const float*)d_in[17];
    const float* abba  = (const float*)d_in[18];
    const float* abma  = (const float*)d_in[19];
    const float* abva  = (const float*)d_in[20];
    const float* abgb  = (const float*)d_in[21];
    const float* abbb  = (const float*)d_in[22];
    const float* abmb  = (const float*)d_in[23];
    const float* abvb  = (const float*)d_in[24];
    const float* anaw  = (const float*)d_in[25];
    const float* anbw  = (const float*)d_in[26];
    const float* s1    = (const float*)d_in[27];
    const float* s2    = (const float*)d_in[28];
    float* out = (float*)d_out;

    setup_kernel<<<(CIN * 9 * NOC + 255) / 256, 256>>>(
        caw, cab, cbw, cbb,
        bag, babt, bam, bav, bbg, bbbt, bbm, bbv,
        attaw, attbw);

    conv_att_kernel<<<dim3(WW / 32, HH / 4, BB), 256>>>(
        x, out, attaw, attab, attbw, attbb,
        abga, abba, abma, abva, abgb, abbb, abmb, abvb);

    map_kernel<<<dim3(WW / 128, HH / 8, BB), dim3(32, 8)>>>(
        out, anaw, anbw, s1, s2);
}

// round 4
// speedup vs baseline: 1.1151x; 1.1151x over previous
#include <cuda_runtime.h>
#include <math.h>

#define HH 256
#define WW 256
#define BB 4
#define CIN 128
#define NOC 128   // 64 (branch a) + 64 (branch b)

typedef unsigned long long u64;

// packed dual-fp32 FMA: d.lo += a.lo*b.lo; d.hi += a.hi*b.hi  (SASS FFMA2)
__device__ __forceinline__ void ffma2(u64 &d, u64 a, u64 b) {
    asm("fma.rn.f32x2 %0, %1, %2, %0;" : "+l"(d) : "l"(a), "l"(b));
}
__device__ __forceinline__ void unpack2(float &lo, float &hi, u64 v) {
    asm("mov.b64 {%0, %1}, %2;" : "=f"(lo), "=f"(hi) : "l"(v));
}

// ---------------- device scratch (no allocations allowed) ----------------
__device__ float g_wT[CIN * 9 * NOC];     // [cin][tap][oc], BN scale folded
__device__ float g_bfold[NOC];            // folded conv bias + BN shift
__device__ float g_attw[NOC];             // per-channel 1x1 attention weight
__device__ float g_att[2 * BB * HH * WW]; // post-BN attention logits [branch][b][h][w]

// ---------------- kernel 0: weight transpose + BN fold ----------------
__global__ void setup_kernel(
    const float* __restrict__ wa, const float* __restrict__ ba,
    const float* __restrict__ wb, const float* __restrict__ bb,
    const float* __restrict__ ga, const float* __restrict__ bta,
    const float* __restrict__ ma, const float* __restrict__ va,
    const float* __restrict__ gb, const float* __restrict__ btb,
    const float* __restrict__ mb, const float* __restrict__ vb,
    const float* __restrict__ attaw, const float* __restrict__ attbw)
{
    int idx = blockIdx.x * blockDim.x + threadIdx.x;
    if (idx < NOC) {
        int oc = idx;
        bool isa = oc < 64;
        int o = isa ? oc : oc - 64;
        float gamma = isa ? ga[o] : gb[o];
        float beta  = isa ? bta[o] : btb[o];
        float mean  = isa ? ma[o] : mb[o];
        float var   = isa ? va[o] : vb[o];
        float A = gamma / sqrtf(var + 1e-3f);
        float bias = isa ? ba[o] : bb[o];
        g_bfold[oc] = (bias - mean) * A + beta;
        g_attw[oc]  = isa ? attaw[o] : attbw[o];
    }
    if (idx < CIN * 9 * NOC) {
        int oc  = idx % NOC;
        int tap = (idx / NOC) % 9;
        int cin = idx / (NOC * 9);
        bool isa = oc < 64;
        int o = isa ? oc : oc - 64;
        float gamma = isa ? ga[o] : gb[o];
        float var   = isa ? va[o] : vb[o];
        float A = gamma / sqrtf(var + 1e-3f);
        const float* w = isa ? wa : wb;
        g_wT[idx] = w[(o * CIN + cin) * 9 + tap] * A;
    }
}

// ---------------- kernel 1: fused dual-branch conv3x3 + BN + 1x1 attention logit ----------------
// Block: 256 threads. Tile: 128 oc x (4h x 32w) pixels.
// Thread: ocg = tid>>4 (16 groups of 8 oc = 4 oc-pairs), pg = tid&15 -> (row 0..3, 8-wide col grp)
// Dynamic smem: ws[8*9*128] floats (weights, oc-contig) | xsd[8][6][70] (input, value-duplicated)
#define WS_FLOATS (8 * 9 * 128)
#define XSD_STRIDE 70
#define XSD_FLOATS (8 * 6 * XSD_STRIDE)
#define SMEM_BYTES ((WS_FLOATS + XSD_FLOATS) * 4)

__global__ void __launch_bounds__(256) conv_att_kernel(
    const float* __restrict__ x, float* __restrict__ out,
    const float* __restrict__ attaw, const float* __restrict__ attab,
    const float* __restrict__ attbw, const float* __restrict__ attbb,
    const float* __restrict__ abga, const float* __restrict__ abba,
    const float* __restrict__ abma, const float* __restrict__ abva,
    const float* __restrict__ abgb, const float* __restrict__ abbb,
    const float* __restrict__ abmb, const float* __restrict__ abvb)
{
    extern __shared__ __align__(16) float smem[];
    float* ws  = smem;               // [ci][tap][oc]
    float* xsd = smem + WS_FLOATS;   // [ci][row][2*col duplicated]

    const int tid = threadIdx.x;
    const int b   = blockIdx.z;
    const int gy0 = blockIdx.y * 4;
    const int gx0 = blockIdx.x * 32;
    const int ocg = tid >> 4;
    const int pg  = tid & 15;
    const int prow = pg >> 2;
    const int c0   = (pg & 3) * 8;

    u64 acc2[4][8];
    #pragma unroll
    for (int op = 0; op < 4; op++)
        #pragma unroll
        for (int p = 0; p < 8; p++) acc2[op][p] = 0ULL;

    for (int cin0 = 0; cin0 < CIN; cin0 += 8) {
        __syncthreads();
        // stage input tile with halo, each value duplicated for (x,x) LDS.64 broadcast pairs
        for (int i = tid; i < 8 * 6 * 34; i += 256) {
            int col = i % 34;
            int row = (i / 34) % 6;
            int ci  = i / 204;
            int gy = gy0 - 1 + row;
            int gx = gx0 - 1 + col;
            float v = 0.f;
            if ((unsigned)gy < HH && (unsigned)gx < WW)
                v = x[(((size_t)b * CIN + cin0 + ci) * HH + gy) * WW + gx];
            float* d = &xsd[(ci * 6 + row) * XSD_STRIDE + 2 * col];
            d[0] = v; d[1] = v;
        }
        // stage weights (coalesced from pre-transposed buffer)
        const float* wsrc = g_wT + cin0 * 9 * NOC;
        for (int i = tid; i < WS_FLOATS; i += 256)
            ws[i] = wsrc[i];
        __syncthreads();

        for (int ci = 0; ci < 8; ci++) {
            #pragma unroll
            for (int rr = 0; rr < 3; rr++) {
                const u64* xrow = (const u64*)&xsd[(ci * 6 + prow + rr) * XSD_STRIDE + 2 * c0];
                u64 xx[10];
                #pragma unroll
                for (int cc = 0; cc < 10; cc++) xx[cc] = xrow[cc];
                #pragma unroll
                for (int op = 0; op < 4; op++) {
                    const u64* wrow = (const u64*)&ws[(ci * 9 + rr * 3) * 128 + ocg * 8 + 2 * op];
                    u64 w0 = wrow[0];       // tap rr*3+0
                    u64 w1 = wrow[64];      // tap rr*3+1 (stride 128 floats = 64 u64)
                    u64 w2 = wrow[128];     // tap rr*3+2
                    #pragma unroll
                    for (int p = 0; p < 8; p++) ffma2(acc2[op][p], xx[p],     w0);
                    #pragma unroll
                    for (int p = 0; p < 8; p++) ffma2(acc2[op][p], xx[p + 1], w1);
                    #pragma unroll
                    for (int p = 0; p < 8; p++) ffma2(acc2[op][p], xx[p + 2], w2);
                }
            }
        }
    }

    // ---------------- epilogue: BN-folded bias, store f, attention partials ----------------
    const int gy  = gy0 + prow;
    const int gxb = gx0 + c0;
    float attp[8];
    #pragma unroll
    for (int p = 0; p < 8; p++) attp[p] = 0.f;

    #pragma unroll
    for (int op = 0; op < 4; op++) {
        int oc0 = ocg * 8 + 2 * op;
        float bf0 = g_bfold[oc0],     bf1 = g_bfold[oc0 + 1];
        float aw0 = g_attw[oc0],      aw1 = g_attw[oc0 + 1];
        float f0[8], f1[8];
        #pragma unroll
        for (int p = 0; p < 8; p++) {
            float lo, hi;
            unpack2(lo, hi, acc2[op][p]);
            f0[p] = lo + bf0;
            f1[p] = hi + bf1;
            attp[p] = fmaf(aw0, f0[p], attp[p]);
            attp[p] = fmaf(aw1, f1[p], attp[p]);
        }
        float* op0 = out + (((size_t)b * NOC + oc0) * HH + gy) * WW + gxb;
        float* op1 = op0 + (size_t)HH * WW;
        *(float4*)op0       = make_float4(f0[0], f0[1], f0[2], f0[3]);
        *(float4*)(op0 + 4) = make_float4(f0[4], f0[5], f0[6], f0[7]);
        *(float4*)op1       = make_float4(f1[0], f1[1], f1[2], f1[3]);
        *(float4*)(op1 + 4) = make_float4(f1[4], f1[5], f1[6], f1[7]);
    }

    __syncthreads();                 // all ws (weight) reads done -> safe to reuse
    float* attpart = ws;             // [16 ocg][128 pix], deterministic reduction
    #pragma unroll
    for (int p = 0; p < 8; p++)
        attpart[ocg * 128 + prow * 32 + c0 + p] = attp[p];
    __syncthreads();

    {
        int branch = tid >> 7;       // 0: a, 1: b
        int pix = tid & 127;
        float s = 0.f;
        #pragma unroll
        for (int g = 0; g < 8; g++)
            s += attpart[(branch * 8 + g) * 128 + pix];
        int row = pix >> 5, col = pix & 31;
        int yy = gy0 + row, xx = gx0 + col;
        float gh = fabsf((float)yy - 127.5f) * (1.f / 128.f);
        float gw = fabsf((float)xx - 127.5f) * (1.f / 128.f);
        const float* awp = branch ? attbw : attaw;
        float pre = s + awp[64] * gh + awp[65] * gw + (branch ? attbb[0] : attab[0]);
        float gm = branch ? abgb[0] : abga[0];
        float bt = branch ? abbb[0] : abba[0];
        float mn = branch ? abmb[0] : abma[0];
        float vr = branch ? abvb[0] : abva[0];
        float av = (pre - mn) * gm / sqrtf(vr + 1e-5f) + bt;
        g_att[(((size_t)branch * BB + b) * HH + yy) * WW + xx] = av;
    }
}

// ---------------- kernel 2: 3x3 attention conv + sigmoid + in-place gating ----------------
__global__ void __launch_bounds__(256) map_kernel(
    float* __restrict__ out,
    const float* __restrict__ wa, const float* __restrict__ wb,
    const float* __restrict__ s1, const float* __restrict__ s2)
{
    __shared__ float swa[36], swb[36];
    int t = threadIdx.y * 32 + threadIdx.x;
    if (t < 36) { swa[t] = wa[t]; swb[t] = wb[t]; }
    __syncthreads();

    int b   = blockIdx.z;
    int gy  = blockIdx.y * 8 + threadIdx.y;
    int gx4 = blockIdx.x * 128 + threadIdx.x * 4;

    const float prmax = 1.41421356237f * (127.5f / 128.f);
    const float prmin = 1.41421356237f * (0.5f / 128.f);
    const float prk = 2.f / (prmax - prmin);
    const float prc = 1.f - prmax * prk;

    float scl1 = s1[0], scl2 = s2[0];
    float mapa[4], mapb[4];
    #pragma unroll
    for (int p = 0; p < 4; p++) {
        int gx = gx4 + p;
        float sa = 0.f, sb = 0.f;
        #pragma unroll
        for (int rr = 0; rr < 3; rr++) {
            int y = gy + rr - 1;
            if ((unsigned)y >= HH) continue;
            #pragma unroll
            for (int ss = 0; ss < 3; ss++) {
                int xq = gx + ss - 1;
                if ((unsigned)xq >= WW) continue;
                float av = g_att[(((size_t)0 * BB + b) * HH + y) * WW + xq];
                float bv = g_att[(((size_t)1 * BB + b) * HH + y) * WW + xq];
                float gh = fabsf((float)y  - 127.5f) * (1.f / 128.f);
                float gw = fabsf((float)xq - 127.5f) * (1.f / 128.f);
                float pr = prk * sqrtf(gh * gh + gw * gw) + prc;
                int tap = rr * 3 + ss;
                sa += swa[tap] * av + swa[9 + tap] * gh + swa[18 + tap] * gw + swa[27 + tap] * pr;
                sb += swb[tap] * bv + swb[9 + tap] * gh + swb[18 + tap] * gw + swb[27 + tap] * pr;
            }
        }
        mapa[p] = scl1 / (1.f + expf(-sa));
        mapb[p] = scl2 / (1.f + expf(-sb));
    }

    size_t base = (((size_t)b * NOC) * HH + gy) * WW + gx4;
    #pragma unroll 4
    for (int oc = 0; oc < NOC; oc++) {
        float4 v = *(float4*)(out + base + (size_t)oc * HH * WW);
        if (oc < 64) { v.x *= mapa[0]; v.y *= mapa[1]; v.z *= mapa[2]; v.w *= mapa[3]; }
        else         { v.x *= mapb[0]; v.y *= mapb[1]; v.z *= mapb[2]; v.w *= mapb[3]; }
        *(float4*)(out + base + (size_t)oc * HH * WW) = v;
    }
}

// ---------------- launch ----------------
extern "C" void kernel_launch(void* const* d_in, const int* in_sizes, int n_in,
                              void* d_out, int out_size)
{
    const float* x     = (const float*)d_in[0];
    const float* caw   = (const float*)d_in[1];
    const float* cab   = (const float*)d_in[2];
    const float* cbw   = (const float*)d_in[3];
    const float* cbb   = (const float*)d_in[4];
    const float* bag   = (const float*)d_in[5];
    const float* babt  = (const float*)d_in[6];
    const float* bam   = (const float*)d_in[7];
    const float* bav   = (const float*)d_in[8];
    const float* bbg   = (const float*)d_in[9];
    const float* bbbt  = (const float*)d_in[10];
    const float* bbm   = (const float*)d_in[11];
    const float* bbv   = (const float*)d_in[12];
    const float* attaw = (const float*)d_in[13];
    const float* attab = (const float*)d_in[14];
    const float* attbw = (const float*)d_in[15];
    const float* attbb = (const float*)d_in[16];
    const float* abga  = (const float*)d_in[17];
    const float* abba  = (const float*)d_in[18];
    const float* abma  = (const float*)d_in[19];
    const float* abva  = (const float*)d_in[20];
    const float* abgb  = (const float*)d_in[21];
    const float* abbb  = (const float*)d_in[22];
    const float* abmb  = (const float*)d_in[23];
    const float* abvb  = (const float*)d_in[24];
    const float* anaw  = (const float*)d_in[25];
    const float* anbw  = (const float*)d_in[26];
    const float* s1    = (const float*)d_in[27];
    const float* s2    = (const float*)d_in[28];
    float* out = (float*)d_out;

    cudaFuncSetAttribute(conv_att_kernel,
                         cudaFuncAttributeMaxDynamicSharedMemorySize, SMEM_BYTES);

    setup_kernel<<<(CIN * 9 * NOC + 255) / 256, 256>>>(
        caw, cab, cbw, cbb,
        bag, babt, bam, bav, bbg, bbbt, bbm, bbv,
        attaw, attbw);

    conv_att_kernel<<<dim3(WW / 32, HH / 4, BB), 256, SMEM_BYTES>>>(
        x, out, attaw, attab, attbw, attbb,
        abga, abba, abma, abva, abgb, abbb, abmb, abvb);

    map_kernel<<<dim3(WW / 128, HH / 8, BB), dim3(32, 8)>>>(
        out, anaw, anbw, s1, s2);
}

// round 6
// speedup vs baseline: 3.5401x; 3.1746x over previous
#include <cuda_runtime.h>
#include <math.h>
#include <stdint.h>

#define HH 256
#define WW 256
#define BB 4
#define CIN 128
#define NOC 128
#define NSTAGE 12

#define A_STRIDE 100                     // floats per oc row in smem (96 + 4 pad)
#define X_STRIDE 136                     // floats per cin row in smem (130 + pad)
#define A_FLOATS (128 * A_STRIDE)        // 12800
#define X_FLOATS (32 * X_STRIDE)         // 4352
#define AOFF(p) ((p) * A_FLOATS * 4)
#define XOFF(p) (2 * A_FLOATS * 4 + (p) * X_FLOATS * 4)
#define DYN_BYTES (2 * A_FLOATS * 4 + 2 * X_FLOATS * 4)   // 137216

// ---------------- device scratch ----------------
__device__ float g_wA[NSTAGE * 128 * 96]; // per-stage [oc][96] tf32-rounded, BN-folded
__device__ float g_bfold[NOC];
__device__ float g_attw[NOC];
__device__ float g_att[2 * BB * HH * WW];

// ---------------- helpers ----------------
__device__ __forceinline__ uint32_t smem_u32(const void* p) {
    uint32_t a;
    asm("{ .reg .u64 t; cvta.to.shared.u64 t, %1; cvt.u32.u64 %0, t; }" : "=r"(a) : "l"(p));
    return a;
}
__device__ __forceinline__ uint32_t f2tf32(float f) {
    uint32_t r; asm("cvt.rna.tf32.f32 %0, %1;" : "=r"(r) : "f"(f)); return r;
}
__device__ __forceinline__ void cp16(uint32_t dst, const void* src) {
    asm volatile("cp.async.cg.shared.global [%0], [%1], 16;" :: "r"(dst), "l"(src));
}
__device__ __forceinline__ void mma8(float* d, const uint32_t* a, uint32_t b0, uint32_t b1) {
    asm volatile(
        "mma.sync.aligned.m16n8k8.row.col.f32.tf32.tf32.f32 "
        "{%0,%1,%2,%3},{%4,%5,%6,%7},{%8,%9},{%0,%1,%2,%3};"
        : "+f"(d[0]), "+f"(d[1]), "+f"(d[2]), "+f"(d[3])
        : "r"(a[0]), "r"(a[1]), "r"(a[2]), "r"(a[3]), "r"(b0), "r"(b1));
}

// ---------------- kernel 0: BN fold + tf32 weight tiles ----------------
__global__ void setup_kernel(
    const float* __restrict__ wa, const float* __restrict__ ba,
    const float* __restrict__ wb, const float* __restrict__ bb,
    const float* __restrict__ ga, const float* __restrict__ bta,
    const float* __restrict__ ma, const float* __restrict__ va,
    const float* __restrict__ gb, const float* __restrict__ btb,
    const float* __restrict__ mb, const float* __restrict__ vb,
    const float* __restrict__ attaw, const float* __restrict__ attbw)
{
    int idx = blockIdx.x * blockDim.x + threadIdx.x;
    if (idx < NOC) {
        int oc = idx;
        bool isa = oc < 64;
        int o = isa ? oc : oc - 64;
        float gamma = isa ? ga[o] : gb[o];
        float beta  = isa ? bta[o] : btb[o];
        float mean  = isa ? ma[o] : mb[o];
        float var   = isa ? va[o] : vb[o];
        float A = gamma / sqrtf(var + 1e-3f);
        float bias = isa ? ba[o] : bb[o];
        g_bfold[oc] = (bias - mean) * A + beta;
        g_attw[oc]  = isa ? attaw[o] : attbw[o];
    }
    if (idx < NSTAGE * 128 * 96) {
        int s  = idx / 12288;
        int r  = idx % 12288;
        int oc = r / 96;
        int k  = r % 96;          // k = dxi*32 + cl
        int dxi = k >> 5;
        int cl  = k & 31;
        int ch  = s / 3;
        int dy  = s % 3;
        int cin = ch * 32 + cl;
        bool isa = oc < 64;
        int o = isa ? oc : oc - 64;
        float gamma = isa ? ga[o] : gb[o];
        float var   = isa ? va[o] : vb[o];
        float A = gamma / sqrtf(var + 1e-3f);
        const float* w = isa ? wa : wb;
        float v = w[((o * CIN + cin) * 3 + dy) * 3 + dxi] * A;
        g_wA[idx] = __uint_as_float(f2tf32(v));
    }
}

// ---------------- kernel 1: mma.sync tf32 conv + BN + 1x1 attention logit ----------------
// grid (2, 256, 4) = (col half, row y, batch). 256 threads, 8 warps.
// warp w: oc0 = (w>>1)*32, pix0 = (w&1)*64. D = 128oc x 128pix, K = 12 stages x 96.
__global__ void __launch_bounds__(256) conv_att_kernel(
    const float* __restrict__ x, float* __restrict__ out,
    const float* __restrict__ attaw, const float* __restrict__ attab,
    const float* __restrict__ attbw, const float* __restrict__ attbb,
    const float* __restrict__ abga, const float* __restrict__ abba,
    const float* __restrict__ abma, const float* __restrict__ abva,
    const float* __restrict__ abgb, const float* __restrict__ abbb,
    const float* __restrict__ abmb, const float* __restrict__ abvb)
{
    extern __shared__ __align__(16) char dyn[];
    const int tid  = threadIdx.x;
    const int b    = blockIdx.z;
    const int y    = blockIdx.y;
    const int c0   = blockIdx.x * 128;
    const int w    = tid >> 5;
    const int lane = tid & 31;
    const int g    = lane >> 2;
    const int tig  = lane & 3;
    const int oc0  = (w >> 1) * 32;
    const int pix0 = (w & 1) * 64;
    const uint32_t dynb = smem_u32(dyn);

    float c[2][8][4];
    #pragma unroll
    for (int mm = 0; mm < 2; mm++)
        #pragma unroll
        for (int nn = 0; nn < 8; nn++)
            #pragma unroll
            for (int k = 0; k < 4; k++) c[mm][nn][k] = 0.f;

    const int cc = tid >> 3, l8 = tid & 7;   // x staging assignment

    // ---- prologue: stage s=0 into buffer 0 ----
    {
        const float* src = g_wA + 0 * 12288 + tid * 4;
        int oc = (tid * 4) / 96, ko = (tid * 4) % 96;
        #pragma unroll
        for (int r = 0; r < 12; r++) {
            cp16(dynb + AOFF(0) + (oc * A_STRIDE + ko) * 4, src);
            src += 1024; ko += 64; oc += 10; if (ko >= 96) { ko -= 96; oc++; }
        }
        asm volatile("cp.async.commit_group;" ::: "memory");

        float xr[17];
        int grow = y + 0 - 1;
        if ((unsigned)grow < HH) {
            const float* xb = x + (((size_t)b * CIN + cc) * HH + grow) * WW;
            #pragma unroll
            for (int i = 0; i < 17; i++) {
                int j = l8 + i * 8;
                int col = c0 - 1 + j;
                xr[i] = (j < 130 && (unsigned)col < WW) ? xb[col] : 0.f;
            }
        } else {
            #pragma unroll
            for (int i = 0; i < 17; i++) xr[i] = 0.f;
        }
        float* Xs = (float*)(dyn + XOFF(0));
        #pragma unroll
        for (int i = 0; i < 17; i++) {
            int j = l8 + i * 8;
            if (j < 130) Xs[cc * X_STRIDE + j] = __uint_as_float(f2tf32(xr[i]));
        }
        asm volatile("cp.async.wait_group 0;" ::: "memory");
        __syncthreads();
    }

    // ---- main loop ----
    for (int s = 0; s < NSTAGE; s++) {
        const int p = s & 1;
        const bool pre = (s + 1 < NSTAGE);
        float xr[17];

        if (pre) {
            // A stage s+1 via cp.async
            const float* src = g_wA + (s + 1) * 12288 + tid * 4;
            int oc = (tid * 4) / 96, ko = (tid * 4) % 96;
            #pragma unroll
            for (int r = 0; r < 12; r++) {
                cp16(dynb + AOFF(p ^ 1) + (oc * A_STRIDE + ko) * 4, src);
                src += 1024; ko += 64; oc += 10; if (ko >= 96) { ko -= 96; oc++; }
            }
            asm volatile("cp.async.commit_group;" ::: "memory");
            // x LDGs for stage s+1 (consumed after compute)
            int sn = s + 1;
            int grow = y + (sn % 3) - 1;
            if ((unsigned)grow < HH) {
                const float* xb = x + (((size_t)b * CIN + (sn / 3) * 32 + cc) * HH + grow) * WW;
                #pragma unroll
                for (int i = 0; i < 17; i++) {
                    int j = l8 + i * 8;
                    int col = c0 - 1 + j;
                    xr[i] = (j < 130 && (unsigned)col < WW) ? xb[col] : 0.f;
                }
            } else {
                #pragma unroll
                for (int i = 0; i < 17; i++) xr[i] = 0.f;
            }
        }

        // ---- compute on buffer p ----
        {
            const float* As = (const float*)(dyn + AOFF(p));
            const float* Xs = (const float*)(dyn + XOFF(p));
            #pragma unroll
            for (int kc = 0; kc < 12; kc++) {
                const int dxi = kc >> 2;
                const int c0k = (kc & 3) * 8;
                const int k0  = kc * 8;
                uint32_t a[2][4];
                #pragma unroll
                for (int mm = 0; mm < 2; mm++) {
                    const float* ap = As + (oc0 + mm * 16 + g) * A_STRIDE + k0 + tig;
                    a[mm][0] = __float_as_uint(ap[0]);
                    a[mm][1] = __float_as_uint(ap[8 * A_STRIDE]);
                    a[mm][2] = __float_as_uint(ap[4]);
                    a[mm][3] = __float_as_uint(ap[8 * A_STRIDE + 4]);
                }
                #pragma unroll
                for (int nn = 0; nn < 8; nn++) {
                    const float* bp = Xs + (c0k + tig) * X_STRIDE + pix0 + nn * 8 + g + dxi;
                    uint32_t b0 = __float_as_uint(bp[0]);
                    uint32_t b1 = __float_as_uint(bp[4 * X_STRIDE]);
                    mma8(c[0][nn], a[0], b0, b1);
                    mma8(c[1][nn], a[1], b0, b1);
                }
            }
        }

        if (pre) {
            float* Xs = (float*)(dyn + XOFF(p ^ 1));
            #pragma unroll
            for (int i = 0; i < 17; i++) {
                int j = l8 + i * 8;
                if (j < 130) Xs[cc * X_STRIDE + j] = __uint_as_float(f2tf32(xr[i]));
            }
        }
        asm volatile("cp.async.wait_group 0;" ::: "memory");
        __syncthreads();
    }

    // ---------------- epilogue ----------------
    float bf[2][2], aw[2][2];
    #pragma unroll
    for (int mm = 0; mm < 2; mm++)
        #pragma unroll
        for (int i2 = 0; i2 < 2; i2++) {
            int ocr = oc0 + mm * 16 + g + i2 * 8;
            bf[mm][i2] = g_bfold[ocr];
            aw[mm][i2] = g_attw[ocr];
        }

    float ap_loc[8][2];
    #pragma unroll
    for (int nn = 0; nn < 8; nn++) { ap_loc[nn][0] = 0.f; ap_loc[nn][1] = 0.f; }

    #pragma unroll
    for (int mm = 0; mm < 2; mm++)
        #pragma unroll
        for (int i2 = 0; i2 < 2; i2++) {
            int ocr = oc0 + mm * 16 + g + i2 * 8;
            float* orow = out + (((size_t)b * NOC + ocr) * HH + y) * WW + c0 + pix0 + 2 * tig;
            #pragma unroll
            for (int nn = 0; nn < 8; nn++) {
                float f0 = c[mm][nn][i2 * 2 + 0] + bf[mm][i2];
                float f1 = c[mm][nn][i2 * 2 + 1] + bf[mm][i2];
                ap_loc[nn][0] = fmaf(aw[mm][i2], f0, ap_loc[nn][0]);
                ap_loc[nn][1] = fmaf(aw[mm][i2], f1, ap_loc[nn][1]);
                *(float2*)(orow + nn * 8) = make_float2(f0, f1);
            }
        }

    // reduce attention partials over g-lanes (same tig), deterministic butterfly
    #pragma unroll
    for (int nn = 0; nn < 8; nn++)
        #pragma unroll
        for (int j = 0; j < 2; j++) {
            float v = ap_loc[nn][j];
            v += __shfl_xor_sync(0xFFFFFFFF, v, 4);
            v += __shfl_xor_sync(0xFFFFFFFF, v, 8);
            v += __shfl_xor_sync(0xFFFFFFFF, v, 16);
            ap_loc[nn][j] = v;
        }
    float* att_part = (float*)dyn;   // [8 warps][64 pix] — A buf0 region, free now
    if (g == 0) {
        #pragma unroll
        for (int nn = 0; nn < 8; nn++) {
            att_part[w * 64 + nn * 8 + 2 * tig + 0] = ap_loc[nn][0];
            att_part[w * 64 + nn * 8 + 2 * tig + 1] = ap_loc[nn][1];
        }
    }
    __syncthreads();

    {
        int branch = tid >> 7;
        int pix = tid & 127;
        int nh = pix >> 6, pl = pix & 63;
        float ssum = att_part[(4 * branch + nh) * 64 + pl]
                   + att_part[(4 * branch + 2 + nh) * 64 + pl];
        int xx = c0 + pix;
        float gh = fabsf((float)y  - 127.5f) * (1.f / 128.f);
        float gw = fabsf((float)xx - 127.5f) * (1.f / 128.f);
        const float* awp = branch ? attbw : attaw;
        float pre = ssum + awp[64] * gh + awp[65] * gw + (branch ? attbb[0] : attab[0]);
        float gm = branch ? abgb[0] : abga[0];
        float bt = branch ? abbb[0] : abba[0];
        float mn = branch ? abmb[0] : abma[0];
        float vr = branch ? abvb[0] : abva[0];
        float av = (pre - mn) * gm / sqrtf(vr + 1e-5f) + bt;
        g_att[(((size_t)branch * BB + b) * HH + y) * WW + xx] = av;
    }
}

// ---------------- kernel 2: 3x3 attention conv + sigmoid + in-place gating ----------------
__global__ void __launch_bounds__(256) map_kernel(
    float* __restrict__ out,
    const float* __restrict__ wa, const float* __restrict__ wb,
    const float* __restrict__ s1, const float* __restrict__ s2)
{
    __shared__ float swa[36], swb[36];
    int t = threadIdx.y * 32 + threadIdx.x;
    if (t < 36) { swa[t] = wa[t]; swb[t] = wb[t]; }
    __syncthreads();

    int b   = blockIdx.z;
    int gy  = blockIdx.y * 8 + threadIdx.y;
    int gx4 = blockIdx.x * 128 + threadIdx.x * 4;

    const float prmax = 1.41421356237f * (127.5f / 128.f);
    const float prmin = 1.41421356237f * (0.5f / 128.f);
    const float prk = 2.f / (prmax - prmin);
    const float prc = 1.f - prmax * prk;

    float scl1 = s1[0], scl2 = s2[0];
    float mapa[4], mapb[4];
    #pragma unroll
    for (int p = 0; p < 4; p++) {
        int gx = gx4 + p;
        float sa = 0.f, sb = 0.f;
        #pragma unroll
        for (int rr = 0; rr < 3; rr++) {
            int yq = gy + rr - 1;
            if ((unsigned)yq >= HH) continue;
            #pragma unroll
            for (int ss = 0; ss < 3; ss++) {
                int xq = gx + ss - 1;
                if ((unsigned)xq >= WW) continue;
                float av = g_att[(((size_t)0 * BB + b) * HH + yq) * WW + xq];
                float bv = g_att[(((size_t)1 * BB + b) * HH + yq) * WW + xq];
                float gh = fabsf((float)yq - 127.5f) * (1.f / 128.f);
                float gw = fabsf((float)xq - 127.5f) * (1.f / 128.f);
                float pr = prk * sqrtf(gh * gh + gw * gw) + prc;
                int tap = rr * 3 + ss;
                sa += swa[tap] * av + swa[9 + tap] * gh + swa[18 + tap] * gw + swa[27 + tap] * pr;
                sb += swb[tap] * bv + swb[9 + tap] * gh + swb[18 + tap] * gw + swb[27 + tap] * pr;
            }
        }
        mapa[p] = scl1 / (1.f + expf(-sa));
        mapb[p] = scl2 / (1.f + expf(-sb));
    }

    size_t base = (((size_t)b * NOC) * HH + gy) * WW + gx4;
    #pragma unroll 4
    for (int oc = 0; oc < NOC; oc++) {
        float4 v = *(float4*)(out + base + (size_t)oc * HH * WW);
        if (oc < 64) { v.x *= mapa[0]; v.y *= mapa[1]; v.z *= mapa[2]; v.w *= mapa[3]; }
        else         { v.x *= mapb[0]; v.y *= mapb[1]; v.z *= mapb[2]; v.w *= mapb[3]; }
        *(float4*)(out + base + (size_t)oc * HH * WW) = v;
    }
}

// ---------------- launch ----------------
extern "C" void kernel_launch(void* const* d_in, const int* in_sizes, int n_in,
                              void* d_out, int out_size)
{
    const float* x     = (const float*)d_in[0];
    const float* caw   = (const float*)d_in[1];
    const float* cab   = (const float*)d_in[2];
    const float* cbw   = (const float*)d_in[3];
    const float* cbb   = (const float*)d_in[4];
    const float* bag   = (const float*)d_in[5];
    const float* babt  = (const float*)d_in[6];
    const float* bam   = (const float*)d_in[7];
    const float* bav   = (const float*)d_in[8];
    const float* bbg   = (const float*)d_in[9];
    const float* bbbt  = (const float*)d_in[10];
    const float* bbm   = (const float*)d_in[11];
    const float* bbv   = (const float*)d_in[12];
    const float* attaw = (const float*)d_in[13];
    const float* attab = (const float*)d_in[14];
    const float* attbw = (const float*)d_in[15];
    const float* attbb = (const float*)d_in[16];
    const float* abga  = (const float*)d_in[17];
    const float* abba  = (const float*)d_in[18];
    const float* abma  = (const float*)d_in[19];
    const float* abva  = (const float*)d_in[20];
    const float* abgb  = (const float*)d_in[21];
    const float* abbb  = (const float*)d_in[22];
    const float* abmb  = (const float*)d_in[23];
    const float* abvb  = (const float*)d_in[24];
    const float* anaw  = (const float*)d_in[25];
    const float* anbw  = (const float*)d_in[26];
    const float* s1    = (const float*)d_in[27];
    const float* s2    = (const float*)d_in[28];
    float* out = (float*)d_out;

    cudaFuncSetAttribute(conv_att_kernel,
                         cudaFuncAttributeMaxDynamicSharedMemorySize, DYN_BYTES);

    setup_kernel<<<(NSTAGE * 128 * 96 + 255) / 256, 256>>>(
        caw, cab, cbw, cbb,
        bag, babt, bam, bav, bbg, bbbt, bbm, bbv,
        attaw, attbw);

    conv_att_kernel<<<dim3(2, HH, BB), 256, DYN_BYTES>>>(
        x, out, attaw, attab, attbw, attbb,
        abga, abba, abma, abva, abgb, abbb, abmb, abvb);

    map_kernel<<<dim3(WW / 128, HH / 8, BB), dim3(32, 8)>>>(
        out, anaw, anbw, s1, s2);
}

// round 7
// speedup vs baseline: 4.4094x; 1.2456x over previous
#include <cuda_runtime.h>
#include <math.h>
#include <stdint.h>

#define HH 256
#define WW 256
#define BB 4
#define CIN 128
#define NOC 128
#define NSTAGE 24                        // (8 cin-chunks of 16) x (3 dy)

#define A_FLOATS 6144                    // per-stage fragment-permuted A: [6 kc][8 blk][32 lane][4]
#define X_STRIDE 136
#define X_FLOATS (16 * X_STRIDE)         // 2176
#define AOFF(p) ((p) * A_FLOATS * 4)
#define XOFF(p) (2 * A_FLOATS * 4 + (p) * X_FLOATS * 4)
#define DYN_BYTES (2 * A_FLOATS * 4 + 2 * X_FLOATS * 4)   // 66560

// ---------------- device scratch ----------------
__device__ float g_wA[NSTAGE * A_FLOATS]; // fragment-permuted, tf32-rounded, BN-folded
__device__ float g_bfold[NOC];
__device__ float g_attw[NOC];
__device__ float g_att[2 * BB * HH * WW];

// ---------------- helpers ----------------
__device__ __forceinline__ uint32_t smem_u32(const void* p) {
    uint32_t a;
    asm("{ .reg .u64 t; cvta.to.shared.u64 t, %1; cvt.u32.u64 %0, t; }" : "=r"(a) : "l"(p));
    return a;
}
__device__ __forceinline__ uint32_t f2tf32(float f) {
    uint32_t r; asm("cvt.rna.tf32.f32 %0, %1;" : "=r"(r) : "f"(f)); return r;
}
__device__ __forceinline__ void cp16(uint32_t dst, const void* src) {
    asm volatile("cp.async.cg.shared.global [%0], [%1], 16;" :: "r"(dst), "l"(src));
}
__device__ __forceinline__ void mma8(float* d, const uint32_t* a, uint32_t b0, uint32_t b1) {
    asm volatile(
        "mma.sync.aligned.m16n8k8.row.col.f32.tf32.tf32.f32 "
        "{%0,%1,%2,%3},{%4,%5,%6,%7},{%8,%9},{%0,%1,%2,%3};"
        : "+f"(d[0]), "+f"(d[1]), "+f"(d[2]), "+f"(d[3])
        : "r"(a[0]), "r"(a[1]), "r"(a[2]), "r"(a[3]), "r"(b0), "r"(b1));
}

// ---------------- kernel 0: BN fold + fragment-permuted tf32 weight tiles ----------------
// g_wA[s][kc][blk][lane][e]:
//   oc = blk*16 + g + 8*(e&1),  k_local = tig + 4*(e>>1)
//   cl = (kc&1)*8 + k_local, dxi = kc>>1, cin = (s/3)*16 + cl, dy = s%3
__global__ void setup_kernel(
    const float* __restrict__ wa, const float* __restrict__ ba,
    const float* __restrict__ wb, const float* __restrict__ bb,
    const float* __restrict__ ga, const float* __restrict__ bta,
    const float* __restrict__ ma, const float* __restrict__ va,
    const float* __restrict__ gb, const float* __restrict__ btb,
    const float* __restrict__ mb, const float* __restrict__ vb,
    const float* __restrict__ attaw, const float* __restrict__ attbw)
{
    int idx = blockIdx.x * blockDim.x + threadIdx.x;
    if (idx < NOC) {
        int oc = idx;
        bool isa = oc < 64;
        int o = isa ? oc : oc - 64;
        float gamma = isa ? ga[o] : gb[o];
        float beta  = isa ? bta[o] : btb[o];
        float mean  = isa ? ma[o] : mb[o];
        float var   = isa ? va[o] : vb[o];
        float A = gamma / sqrtf(var + 1e-3f);
        float bias = isa ? ba[o] : bb[o];
        g_bfold[oc] = (bias - mean) * A + beta;
        g_attw[oc]  = isa ? attaw[o] : attbw[o];
    }
    if (idx < NSTAGE * A_FLOATS) {
        int e    = idx & 3;
        int lane = (idx >> 2) & 31;
        int blk  = (idx >> 7) & 7;
        int kc   = (idx >> 10) % 6;
        int s    = idx / A_FLOATS;
        int g    = lane >> 2;
        int tig  = lane & 3;
        int oc = blk * 16 + g + ((e & 1) ? 8 : 0);
        int kl = tig + ((e & 2) ? 4 : 0);
        int cl = (kc & 1) * 8 + kl;
        int dxi = kc >> 1;
        int cin = (s / 3) * 16 + cl;
        int dy  = s % 3;
        bool isa = oc < 64;
        int o = isa ? oc : oc - 64;
        float gamma = isa ? ga[o] : gb[o];
        float var   = isa ? va[o] : vb[o];
        float A = gamma / sqrtf(var + 1e-3f);
        const float* w = isa ? wa : wb;
        float v = w[((o * CIN + cin) * 3 + dy) * 3 + dxi] * A;
        g_wA[idx] = __uint_as_float(f2tf32(v));
    }
}

// ---------------- kernel 1: mma.sync tf32 conv + BN + 1x1 attention logit ----------------
// grid (2, 256, 4) = (col half, row y, batch). 256 threads, 8 warps, 2 CTAs/SM.
// warp w: oc0 = (w>>1)*32, pix0 = (w&1)*64. D = 128oc x 128pix, K = 24 stages x 48.
__global__ void __launch_bounds__(256, 2) conv_att_kernel(
    const float* __restrict__ x, float* __restrict__ out,
    const float* __restrict__ attaw, const float* __restrict__ attab,
    const float* __restrict__ attbw, const float* __restrict__ attbb,
    const float* __restrict__ abga, const float* __restrict__ abba,
    const float* __restrict__ abma, const float* __restrict__ abva,
    const float* __restrict__ abgb, const float* __restrict__ abbb,
    const float* __restrict__ abmb, const float* __restrict__ abvb)
{
    extern __shared__ __align__(16) char dyn[];
    const int tid  = threadIdx.x;
    const int b    = blockIdx.z;
    const int y    = blockIdx.y;
    const int c0   = blockIdx.x * 128;
    const int w    = tid >> 5;
    const int lane = tid & 31;
    const int g    = lane >> 2;
    const int tig  = lane & 3;
    const int oc0  = (w >> 1) * 32;
    const int pix0 = (w & 1) * 64;
    const int blk0 = (w >> 1) * 2;
    const uint32_t dynb = smem_u32(dyn);

    float c[2][8][4];
    #pragma unroll
    for (int mm = 0; mm < 2; mm++)
        #pragma unroll
        for (int nn = 0; nn < 8; nn++)
            #pragma unroll
            for (int k = 0; k < 4; k++) c[mm][nn][k] = 0.f;

    const int cc = tid >> 4, l16 = tid & 15;   // x staging: 16 rows x 16 threads

    // ---- prologue: stage s=0 into buffer 0 ----
    {
        const char* src = (const char*)(g_wA) + tid * 16;
        #pragma unroll
        for (int r = 0; r < 6; r++)
            cp16(dynb + AOFF(0) + tid * 16 + r * 4096, src + r * 4096);
        asm volatile("cp.async.commit_group;" ::: "memory");

        float xr[9];
        int grow = y - 1;
        if ((unsigned)grow < HH) {
            const float* xb = x + (((size_t)b * CIN + cc) * HH + grow) * WW;
            #pragma unroll
            for (int i = 0; i < 9; i++) {
                int j = l16 + i * 16;
                int col = c0 - 1 + j;
                xr[i] = (j < 130 && (unsigned)col < WW) ? xb[col] : 0.f;
            }
        } else {
            #pragma unroll
            for (int i = 0; i < 9; i++) xr[i] = 0.f;
        }
        float* Xs = (float*)(dyn + XOFF(0));
        #pragma unroll
        for (int i = 0; i < 9; i++) {
            int j = l16 + i * 16;
            if (j < 130) Xs[cc * X_STRIDE + j] = __uint_as_float(f2tf32(xr[i]));
        }
        asm volatile("cp.async.wait_group 0;" ::: "memory");
        __syncthreads();
    }

    // ---- main loop ----
    for (int s = 0; s < NSTAGE; s++) {
        const int p = s & 1;
        const bool pre = (s + 1 < NSTAGE);
        float xr[9];

        if (pre) {
            const char* src = (const char*)(g_wA + (s + 1) * A_FLOATS) + tid * 16;
            #pragma unroll
            for (int r = 0; r < 6; r++)
                cp16(dynb + AOFF(p ^ 1) + tid * 16 + r * 4096, src + r * 4096);
            asm volatile("cp.async.commit_group;" ::: "memory");
            int sn = s + 1;
            int grow = y + (sn % 3) - 1;
            if ((unsigned)grow < HH) {
                const float* xb = x + (((size_t)b * CIN + (sn / 3) * 16 + cc) * HH + grow) * WW;
                #pragma unroll
                for (int i = 0; i < 9; i++) {
                    int j = l16 + i * 16;
                    int col = c0 - 1 + j;
                    xr[i] = (j < 130 && (unsigned)col < WW) ? xb[col] : 0.f;
                }
            } else {
                #pragma unroll
                for (int i = 0; i < 9; i++) xr[i] = 0.f;
            }
        }

        // ---- compute on buffer p ----
        {
            const float4* As = (const float4*)(dyn + AOFF(p));
            const float* Xs = (const float*)(dyn + XOFF(p));
            #pragma unroll
            for (int kc = 0; kc < 6; kc++) {
                const int dxi = kc >> 1;
                const int c0k = (kc & 1) * 8;
                uint32_t a[2][4];
                #pragma unroll
                for (int mm = 0; mm < 2; mm++) {
                    float4 av = As[(kc * 8 + blk0 + mm) * 32 + lane];
                    a[mm][0] = __float_as_uint(av.x);
                    a[mm][1] = __float_as_uint(av.y);
                    a[mm][2] = __float_as_uint(av.z);
                    a[mm][3] = __float_as_uint(av.w);
                }
                #pragma unroll
                for (int nn = 0; nn < 8; nn++) {
                    const float* bp = Xs + (c0k + tig) * X_STRIDE + pix0 + nn * 8 + g + dxi;
                    uint32_t b0 = __float_as_uint(bp[0]);
                    uint32_t b1 = __float_as_uint(bp[4 * X_STRIDE]);
                    mma8(c[0][nn], a[0], b0, b1);
                    mma8(c[1][nn], a[1], b0, b1);
                }
            }
        }

        if (pre) {
            float* Xs = (float*)(dyn + XOFF(p ^ 1));
            #pragma unroll
            for (int i = 0; i < 9; i++) {
                int j = l16 + i * 16;
                if (j < 130) Xs[cc * X_STRIDE + j] = __uint_as_float(f2tf32(xr[i]));
            }
        }
        asm volatile("cp.async.wait_group 0;" ::: "memory");
        __syncthreads();
    }

    // ---------------- epilogue ----------------
    float bf[2][2], aw[2][2];
    #pragma unroll
    for (int mm = 0; mm < 2; mm++)
        #pragma unroll
        for (int i2 = 0; i2 < 2; i2++) {
            int ocr = oc0 + mm * 16 + g + i2 * 8;
            bf[mm][i2] = g_bfold[ocr];
            aw[mm][i2] = g_attw[ocr];
        }

    float ap_loc[8][2];
    #pragma unroll
    for (int nn = 0; nn < 8; nn++) { ap_loc[nn][0] = 0.f; ap_loc[nn][1] = 0.f; }

    #pragma unroll
    for (int mm = 0; mm < 2; mm++)
        #pragma unroll
        for (int i2 = 0; i2 < 2; i2++) {
            int ocr = oc0 + mm * 16 + g + i2 * 8;
            float* orow = out + (((size_t)b * NOC + ocr) * HH + y) * WW + c0 + pix0 + 2 * tig;
            #pragma unroll
            for (int nn = 0; nn < 8; nn++) {
                float f0 = c[mm][nn][i2 * 2 + 0] + bf[mm][i2];
                float f1 = c[mm][nn][i2 * 2 + 1] + bf[mm][i2];
                ap_loc[nn][0] = fmaf(aw[mm][i2], f0, ap_loc[nn][0]);
                ap_loc[nn][1] = fmaf(aw[mm][i2], f1, ap_loc[nn][1]);
                *(float2*)(orow + nn * 8) = make_float2(f0, f1);
            }
        }

    // reduce attention partials over g-lanes (same tig), deterministic butterfly
    #pragma unroll
    for (int nn = 0; nn < 8; nn++)
        #pragma unroll
        for (int j = 0; j < 2; j++) {
            float v = ap_loc[nn][j];
            v += __shfl_xor_sync(0xFFFFFFFF, v, 4);
            v += __shfl_xor_sync(0xFFFFFFFF, v, 8);
            v += __shfl_xor_sync(0xFFFFFFFF, v, 16);
            ap_loc[nn][j] = v;
        }
    float* att_part = (float*)dyn;   // [8 warps][64 pix] — A buf0 region, free now
    if (g == 0) {
        #pragma unroll
        for (int nn = 0; nn < 8; nn++) {
            att_part[w * 64 + nn * 8 + 2 * tig + 0] = ap_loc[nn][0];
            att_part[w * 64 + nn * 8 + 2 * tig + 1] = ap_loc[nn][1];
        }
    }
    __syncthreads();

    {
        int branch = tid >> 7;
        int pix = tid & 127;
        int nh = pix >> 6, pl = pix & 63;
        float ssum = att_part[(4 * branch + nh) * 64 + pl]
                   + att_part[(4 * branch + 2 + nh) * 64 + pl];
        int xx = c0 + pix;
        float gh = fabsf((float)y  - 127.5f) * (1.f / 128.f);
        float gw = fabsf((float)xx - 127.5f) * (1.f / 128.f);
        const float* awp = branch ? attbw : attaw;
        float pre = ssum + awp[64] * gh + awp[65] * gw + (branch ? attbb[0] : attab[0]);
        float gm = branch ? abgb[0] : abga[0];
        float bt = branch ? abbb[0] : abba[0];
        float mn = branch ? abmb[0] : abma[0];
        float vr = branch ? abvb[0] : abva[0];
        float av = (pre - mn) * gm / sqrtf(vr + 1e-5f) + bt;
        g_att[(((size_t)branch * BB + b) * HH + y) * WW + xx] = av;
    }
}

// ---------------- kernel 2: 3x3 attention conv + sigmoid + in-place gating ----------------
__global__ void __launch_bounds__(256) map_kernel(
    float* __restrict__ out,
    const float* __restrict__ wa, const float* __restrict__ wb,
    const float* __restrict__ s1, const float* __restrict__ s2)
{
    __shared__ float swa[36], swb[36];
    int t = threadIdx.y * 32 + threadIdx.x;
    if (t < 36) { swa[t] = wa[t]; swb[t] = wb[t]; }
    __syncthreads();

    int b   = blockIdx.z;
    int gy  = blockIdx.y * 8 + threadIdx.y;
    int gx4 = blockIdx.x * 128 + threadIdx.x * 4;

    const float prmax = 1.41421356237f * (127.5f / 128.f);
    const float prmin = 1.41421356237f * (0.5f / 128.f);
    const float prk = 2.f / (prmax - prmin);
    const float prc = 1.f - prmax * prk;

    float scl1 = s1[0], scl2 = s2[0];
    float mapa[4], mapb[4];
    #pragma unroll
    for (int p = 0; p < 4; p++) {
        int gx = gx4 + p;
        float sa = 0.f, sb = 0.f;
        #pragma unroll
        for (int rr = 0; rr < 3; rr++) {
            int yq = gy + rr - 1;
            if ((unsigned)yq >= HH) continue;
            #pragma unroll
            for (int ss = 0; ss < 3; ss++) {
                int xq = gx + ss - 1;
                if ((unsigned)xq >= WW) continue;
                float av = g_att[(((size_t)0 * BB + b) * HH + yq) * WW + xq];
                float bv = g_att[(((size_t)1 * BB + b) * HH + yq) * WW + xq];
                float gh = fabsf((float)yq - 127.5f) * (1.f / 128.f);
                float gw = fabsf((float)xq - 127.5f) * (1.f / 128.f);
                float pr = prk * sqrtf(gh * gh + gw * gw) + prc;
                int tap = rr * 3 + ss;
                sa += swa[tap] * av + swa[9 + tap] * gh + swa[18 + tap] * gw + swa[27 + tap] * pr;
                sb += swb[tap] * bv + swb[9 + tap] * gh + swb[18 + tap] * gw + swb[27 + tap] * pr;
            }
        }
        mapa[p] = scl1 / (1.f + expf(-sa));
        mapb[p] = scl2 / (1.f + expf(-sb));
    }

    size_t base = (((size_t)b * NOC) * HH + gy) * WW + gx4;
    #pragma unroll 4
    for (int oc = 0; oc < NOC; oc++) {
        float4 v = *(float4*)(out + base + (size_t)oc * HH * WW);
        if (oc < 64) { v.x *= mapa[0]; v.y *= mapa[1]; v.z *= mapa[2]; v.w *= mapa[3]; }
        else         { v.x *= mapb[0]; v.y *= mapb[1]; v.z *= mapb[2]; v.w *= mapb[3]; }
        *(float4*)(out + base + (size_t)oc * HH * WW) = v;
    }
}

// ---------------- launch ----------------
extern "C" void kernel_launch(void* const* d_in, const int* in_sizes, int n_in,
                              void* d_out, int out_size)
{
    const float* x     = (const float*)d_in[0];
    const float* caw   = (const float*)d_in[1];
    const float* cab   = (const float*)d_in[2];
    const float* cbw   = (const float*)d_in[3];
    const float* cbb   = (const float*)d_in[4];
    const float* bag   = (const float*)d_in[5];
    const float* babt  = (const float*)d_in[6];
    const float* bam   = (const float*)d_in[7];
    const float* bav   = (const float*)d_in[8];
    const float* bbg   = (const float*)d_in[9];
    const float* bbbt  = (const float*)d_in[10];
    const float* bbm   = (const float*)d_in[11];
    const float* bbv   = (const float*)d_in[12];
    const float* attaw = (const float*)d_in[13];
    const float* attab = (const float*)d_in[14];
    const float* attbw = (const float*)d_in[15];
    const float* attbb = (const float*)d_in[16];
    const float* abga  = (const float*)d_in[17];
    const float* abba  = (const float*)d_in[18];
    const float* abma  = (const float*)d_in[19];
    const float* abva  = (const float*)d_in[20];
    const float* abgb  = (const float*)d_in[21];
    const float* abbb  = (const float*)d_in[22];
    const float* abmb  = (const float*)d_in[23];
    const float* abvb  = (const float*)d_in[24];
    const float* anaw  = (const float*)d_in[25];
    const float* anbw  = (const float*)d_in[26];
    const float* s1    = (const float*)d_in[27];
    const float* s2    = (const float*)d_in[28];
    float* out = (float*)d_out;

    cudaFuncSetAttribute(conv_att_kernel,
                         cudaFuncAttributeMaxDynamicSharedMemorySize, DYN_BYTES);

    setup_kernel<<<(NSTAGE * A_FLOATS + 255) / 256, 256>>>(
        caw, cab, cbw, cbb,
        bag, babt, bam, bav, bbg, bbbt, bbm, bbv,
        attaw, attbw);

    conv_att_kernel<<<dim3(2, HH, BB), 256, DYN_BYTES>>>(
        x, out, attaw, attab, attbw, attbb,
        abga, abba, abma, abva, abgb, abbb, abmb, abvb);

    map_kernel<<<dim3(WW / 128, HH / 8, BB), dim3(32, 8)>>>(
        out, anaw, anbw, s1, s2);
}